// round 16
// baseline (speedup 1.0000x reference)
#include <cuda_runtime.h>
#include <math.h>

#define B_ 256
#define T_ 250
#define I_ 700
#define H_ 128
#define O_ 20

// Scratch: xin[b][t][h] = (x @ w_ih1 + b_ih1), 32.77 MB static device array
__device__ float g_xin[B_ * T_ * H_];

// ---------------------------------------------------------------------------
// Kernel 1: xin = x @ w_ih1 + b_ih1   (M=64000, K=700, N=128)
// EXACT-FP32 SGEMM, per-element fully-serial fmaf ascending k (bit-identical
// to R12/R14). Double-buffered SMEM pipeline; float4 global loads for A and B.
// ---------------------------------------------------------------------------
__global__ __launch_bounds__(256) void gemm_xin_kernel(
    const float* __restrict__ x, const float* __restrict__ w,
    const float* __restrict__ bias)
{
    __shared__ float As[2][8][128];
    __shared__ float Bs[2][8][128];
    const int tid = threadIdx.x;
    const int m0  = blockIdx.x * 128;
    const int tr = tid >> 4, tc = tid & 15;            // 16x16 thread grid, 8x8 each
    const int arow = tid >> 1, acol = (tid & 1) * 4;   // A loads: float4 (k 4-aligned)
    const int brow = tid >> 5, bcol = (tid & 31) * 4;  // B loads: float4
    const float* xrow = x + (size_t)(m0 + arow) * I_;
    const int NT = (I_ + 7) / 8;                       // 88 k-tiles

    float c[8][8];
#pragma unroll
    for (int i = 0; i < 8; ++i)
#pragma unroll
        for (int j = 0; j < 8; ++j) c[i][j] = 0.f;

    // preload tile 0 into buffer 0 (k = acol < 700 always)
    {
        float4 va = *reinterpret_cast<const float4*>(xrow + acol);
        As[0][acol + 0][arow] = va.x; As[0][acol + 1][arow] = va.y;
        As[0][acol + 2][arow] = va.z; As[0][acol + 3][arow] = va.w;
        float4 vb = *reinterpret_cast<const float4*>(w + (size_t)brow * H_ + bcol);
        Bs[0][brow][bcol + 0] = vb.x; Bs[0][brow][bcol + 1] = vb.y;
        Bs[0][brow][bcol + 2] = vb.z; Bs[0][brow][bcol + 3] = vb.w;
    }
    __syncthreads();

    for (int kt = 0; kt < NT; ++kt) {
        const int cur = kt & 1, nxt = cur ^ 1;
        // prefetch next tile into registers (overlaps with compute below)
        float4 pa = make_float4(0.f, 0.f, 0.f, 0.f);
        float4 pb = make_float4(0.f, 0.f, 0.f, 0.f);
        if (kt + 1 < NT) {
            int ka = (kt + 1) * 8 + acol;     // multiple of 4; I_=700 is too -> no straddle
            if (ka < I_) pa = *reinterpret_cast<const float4*>(xrow + ka);
            int kb = (kt + 1) * 8 + brow;
            if (kb < I_) pb = *reinterpret_cast<const float4*>(w + (size_t)kb * H_ + bcol);
        }
        // compute current tile: serial ascending k per output (bit-exact)
#pragma unroll
        for (int k = 0; k < 8; ++k) {
            float4 a0 = *reinterpret_cast<const float4*>(&As[cur][k][tr * 8]);
            float4 a1 = *reinterpret_cast<const float4*>(&As[cur][k][tr * 8 + 4]);
            float4 b0 = *reinterpret_cast<const float4*>(&Bs[cur][k][tc * 8]);
            float4 b1 = *reinterpret_cast<const float4*>(&Bs[cur][k][tc * 8 + 4]);
            float a[8] = {a0.x, a0.y, a0.z, a0.w, a1.x, a1.y, a1.z, a1.w};
            float bb[8] = {b0.x, b0.y, b0.z, b0.w, b1.x, b1.y, b1.z, b1.w};
#pragma unroll
            for (int i = 0; i < 8; ++i)
#pragma unroll
                for (int j = 0; j < 8; ++j) c[i][j] = fmaf(a[i], bb[j], c[i][j]);
        }
        // store prefetched tile into the other buffer
        if (kt + 1 < NT) {
            As[nxt][acol + 0][arow] = pa.x; As[nxt][acol + 1][arow] = pa.y;
            As[nxt][acol + 2][arow] = pa.z; As[nxt][acol + 3][arow] = pa.w;
            Bs[nxt][brow][bcol + 0] = pb.x; Bs[nxt][brow][bcol + 1] = pb.y;
            Bs[nxt][brow][bcol + 2] = pb.z; Bs[nxt][brow][bcol + 3] = pb.w;
        }
        __syncthreads();
    }
#pragma unroll
    for (int i = 0; i < 8; ++i) {
        int m = m0 + tr * 8 + i;
        float* orow = g_xin + (size_t)m * H_;
#pragma unroll
        for (int j = 0; j < 8; j += 4) {
            int n = tc * 8 + j;
            float4 v;
            v.x = __fadd_rn(c[i][j + 0], bias[n + 0]);
            v.y = __fadd_rn(c[i][j + 1], bias[n + 1]);
            v.z = __fadd_rn(c[i][j + 2], bias[n + 2]);
            v.w = __fadd_rn(c[i][j + 3], bias[n + 3]);
            *reinterpret_cast<float4*>(orow + n) = v;
        }
    }
}

// ---------------------------------------------------------------------------
// Kernel 2: warp-per-row scan, R15 optimizations:
//  - PERMUTED weight layout: w[j][h] stored at j*128 + (h%32)*4 + h/32, so a
//    lane's 4 units (h = g*32+lane) are one float4 -> 1 LDS.128 per spike.
//  - mv11 and mv22 FUSED into one 64-bit bit-scan (both use prev-step masks);
//    their FADD chains interleave. Per-matrix add order unchanged (asc w, j).
//  - mv12 / readout-dot unrolled x2 (loads ahead of the ordered adds).
// All per-unit arithmetic sequences bit-identical to the R12/R14 passing runs.
// ---------------------------------------------------------------------------
#define SCAN_SMEM_FLOATS (3 * H_ * H_ + H_ * O_)
#define SCAN_SMEM_BYTES  (SCAN_SMEM_FLOATS * 4)

__global__ __launch_bounds__(128, 1) void scan_kernel(
    const float* __restrict__ mask,
    const float* __restrict__ w_h1h1, const float* __restrict__ b_h1h1,
    const float* __restrict__ w_h1h2, const float* __restrict__ b_h1h2,
    const float* __restrict__ w_h2h2, const float* __restrict__ b_h2h2,
    const float* __restrict__ w_h2o,  const float* __restrict__ b_h2o,
    const float* __restrict__ tau_adp_h1, const float* __restrict__ tau_adp_h2,
    const float* __restrict__ tau_m_h1,   const float* __restrict__ tau_m_h2,
    const float* __restrict__ tau_m_o,
    const float* __restrict__ hid1_mem0,  const float* __restrict__ hid2_mem0,
    const float* __restrict__ out_mem0,
    float* __restrict__ out)
{
    extern __shared__ float sm[];
    float* sw11 = sm;                    // 128x128 permuted (mask-applied)
    float* sw12 = sw11 + H_ * H_;        // 128x128 permuted
    float* sw22 = sw12 + H_ * H_;        // 128x128 permuted (mask-applied)
    float* sw2o = sw22 + H_ * H_;        // 128x20  [j][O]

    const int tid  = threadIdx.x;
    const int wid  = tid >> 5;
    const int lane = tid & 31;
    const int b    = blockIdx.x * 4 + wid;

    for (int i = tid; i < H_ * H_; i += 128) {
        int j = i >> 7, h = i & 127;
        int p = (j << 7) + ((h & 31) << 2) + (h >> 5);   // permuted column
        sw11[p] = __fmul_rn(w_h1h1[i], mask[i]);
        sw12[p] = w_h1h2[i];
        sw22[p] = __fmul_rn(w_h2h2[i], mask[H_ * H_ + i]);
    }
    for (int i = tid; i < H_ * O_; i += 128) sw2o[i] = w_h2o[i];
    __syncthreads();   // weights ready (only block-wide sync)

    // per-unit constants/state, 4 units per lane: h = g*32 + lane
    float a1[4], r1[4], a2[4], r2[4], c1[4], c12[4], c22[4];
    float h1m[4], h2m[4], ab1[4], ab2[4], s1p[4], s2p[4], s1c[4], s2c[4];
#pragma unroll
    for (int g = 0; g < 4; ++g) {
        int h = g * 32 + lane;
        a1[g] = (float)exp((double)__fdiv_rn(-1.f, tau_m_h1[h]));
        r1[g] = (float)exp((double)__fdiv_rn(-1.f, tau_adp_h1[h]));
        a2[g] = (float)exp((double)__fdiv_rn(-1.f, tau_m_h2[h]));
        r2[g] = (float)exp((double)__fdiv_rn(-1.f, tau_adp_h2[h]));
        c1[g]  = b_h1h1[h];
        c12[g] = b_h1h2[h];
        c22[g] = b_h2h2[h];
        h1m[g] = hid1_mem0[b * H_ + h];
        h2m[g] = hid2_mem0[b * H_ + h];
        ab1[g] = 0.01f; ab2[g] = 0.01f;
        s1p[g] = 0.f; s2p[g] = 0.f; s1c[g] = 0.f; s2c[g] = 0.f;
    }
    const int lo = (lane < O_) ? lane : (O_ - 1);   // clamped readout column
    float ao = 1.f, om = 0.f, accO = 0.f, bo = 0.f;
    if (lane < O_) {
        ao = (float)exp((double)__fdiv_rn(-1.f, tau_m_o[lane]));
        om = out_mem0[b * O_ + lane];
        bo = b_h2o[lane];
    }

    unsigned m1w[4] = {0u, 0u, 0u, 0u};
    unsigned m2w[4] = {0u, 0u, 0u, 0u};

    const int l4 = lane << 2;
    float xv[4], xn[4];
#pragma unroll
    for (int g = 0; g < 4; ++g) xn[g] = g_xin[(size_t)(b * T_) * H_ + g * 32 + lane];

    for (int t = 0; t < T_; ++t) {
#pragma unroll
        for (int g = 0; g < 4; ++g) xv[g] = xn[g];
        if (t + 1 < T_) {
#pragma unroll
            for (int g = 0; g < 4; ++g)
                xn[g] = g_xin[(size_t)(b * T_ + t + 1) * H_ + g * 32 + lane];
        }

        // ---- fused mv11 (m1 prev) + mv22 (m2 prev): 64-bit scan, 8 chains ----
        float acc[4] = {0.f, 0.f, 0.f, 0.f};
        float a22[4] = {0.f, 0.f, 0.f, 0.f};
#pragma unroll
        for (int w = 0; w < 4; ++w) {
            unsigned long long bits =
                ((unsigned long long)m2w[w] << 32) | (unsigned long long)m1w[w];
            const float* b11 = sw11 + (w * 32) * H_ + l4;
            const float* b22 = sw22 + (w * 32) * H_ + l4;
            while (bits) {
                int j64 = __ffsll((long long)bits) - 1; bits &= bits - 1;
                if (j64 < 32) {      // warp-uniform branch (ballot masks)
                    float4 v = *reinterpret_cast<const float4*>(b11 + (j64 << 7));
                    acc[0] = __fadd_rn(acc[0], v.x); acc[1] = __fadd_rn(acc[1], v.y);
                    acc[2] = __fadd_rn(acc[2], v.z); acc[3] = __fadd_rn(acc[3], v.w);
                } else {
                    float4 v = *reinterpret_cast<const float4*>(b22 + ((j64 - 32) << 7));
                    a22[0] = __fadd_rn(a22[0], v.x); a22[1] = __fadd_rn(a22[1], v.y);
                    a22[2] = __fadd_rn(a22[2], v.z); a22[3] = __fadd_rn(a22[3], v.w);
                }
            }
        }

        // ---- layer 1 dynamics ----
        float ns1[4];
#pragma unroll
        for (int g = 0; g < 4; ++g) {
            float i1 = __fadd_rn(__fadd_rn(xv[g], acc[g]), c1[g]);
            ab1[g] = __fadd_rn(__fmul_rn(r1[g], ab1[g]),
                               __fmul_rn(__fsub_rn(1.f, r1[g]), s1p[g]));
            float B1 = __fadd_rn(0.01f, __fmul_rn(1.8f, ab1[g]));
            h1m[g] = __fsub_rn(__fadd_rn(__fmul_rn(h1m[g], a1[g]),
                                         __fmul_rn(__fsub_rn(1.f, a1[g]), i1)),
                               __fmul_rn(B1, s1p[g]));
            ns1[g] = __fsub_rn(h1m[g], B1) > 0.f ? 1.f : 0.f;
            s1c[g] += ns1[g];
            s1p[g] = ns1[g];
        }
#pragma unroll
        for (int g = 0; g < 4; ++g)
            m1w[g] = __ballot_sync(0xffffffffu, ns1[g] != 0.f);

        // ---- mv12 (m1 cur), unroll x2 ----
        float a12[4] = {0.f, 0.f, 0.f, 0.f};
#pragma unroll
        for (int w = 0; w < 4; ++w) {
            unsigned bits = m1w[w];
            const float* bb = sw12 + (w * 32) * H_ + l4;
            while (bits) {
                int j0 = __ffs(bits) - 1; bits &= bits - 1;
                if (bits) {
                    int j1 = __ffs(bits) - 1; bits &= bits - 1;
                    float4 v0 = *reinterpret_cast<const float4*>(bb + (j0 << 7));
                    float4 v1 = *reinterpret_cast<const float4*>(bb + (j1 << 7));
                    a12[0] = __fadd_rn(__fadd_rn(a12[0], v0.x), v1.x);
                    a12[1] = __fadd_rn(__fadd_rn(a12[1], v0.y), v1.y);
                    a12[2] = __fadd_rn(__fadd_rn(a12[2], v0.z), v1.z);
                    a12[3] = __fadd_rn(__fadd_rn(a12[3], v0.w), v1.w);
                } else {
                    float4 v0 = *reinterpret_cast<const float4*>(bb + (j0 << 7));
                    a12[0] = __fadd_rn(a12[0], v0.x);
                    a12[1] = __fadd_rn(a12[1], v0.y);
                    a12[2] = __fadd_rn(a12[2], v0.z);
                    a12[3] = __fadd_rn(a12[3], v0.w);
                }
            }
        }

        // ---- layer 2 dynamics ----
        float ns2[4];
#pragma unroll
        for (int g = 0; g < 4; ++g) {
            float i2 = __fadd_rn(__fadd_rn(__fadd_rn(a12[g], c12[g]), a22[g]), c22[g]);
            ab2[g] = __fadd_rn(__fmul_rn(r2[g], ab2[g]),
                               __fmul_rn(__fsub_rn(1.f, r2[g]), s2p[g]));
            float B2 = __fadd_rn(0.01f, __fmul_rn(1.8f, ab2[g]));
            h2m[g] = __fsub_rn(__fadd_rn(__fmul_rn(h2m[g], a2[g]),
                                         __fmul_rn(__fsub_rn(1.f, a2[g]), i2)),
                               __fmul_rn(B2, s2p[g]));
            ns2[g] = __fsub_rn(h2m[g], B2) > 0.f ? 1.f : 0.f;
            s2c[g] += ns2[g];
            s2p[g] = ns2[g];
        }
#pragma unroll
        for (int g = 0; g < 4; ++g)
            m2w[g] = __ballot_sync(0xffffffffu, ns2[g] != 0.f);

        // ---- readout + running softmax (in-warp) ----
        {
            float dot = 0.f;
#pragma unroll
            for (int w = 0; w < 4; ++w) {
                unsigned bits = m2w[w];
                const float* rb = sw2o + (w * 32) * O_ + lo;
                while (bits) {
                    int j0 = __ffs(bits) - 1; bits &= bits - 1;
                    if (bits) {
                        int j1 = __ffs(bits) - 1; bits &= bits - 1;
                        float t0 = rb[j0 * O_], t1 = rb[j1 * O_];
                        dot = __fadd_rn(__fadd_rn(dot, t0), t1);
                    } else {
                        dot = __fadd_rn(dot, rb[j0 * O_]);
                    }
                }
            }
            if (lane < O_) {
                float io = __fadd_rn(dot, bo);
                om = __fadd_rn(__fmul_rn(ao, om),
                               __fmul_rn(__fsub_rn(1.f, ao), io));
            }
            float v = (lane < O_) ? om : -3.402823466e38f;
#pragma unroll
            for (int off = 16; off; off >>= 1)
                v = fmaxf(v, __shfl_xor_sync(0xffffffffu, v, off));
            float e = (lane < O_) ? expf(__fsub_rn(om, v)) : 0.f;
            float s = 0.f;
#pragma unroll
            for (int j = 0; j < O_; ++j)
                s = __fadd_rn(s, __shfl_sync(0xffffffffu, e, j));
            if (t > 10 && lane < O_) accO = __fadd_rn(accO, __fdiv_rn(e, s));
        }
    }

    // outputs: [acc (B,O)] [s1/T (B,H)] [s2/T (B,H)] [A_norm]
    if (lane < O_) out[b * O_ + lane] = accO;
#pragma unroll
    for (int g = 0; g < 4; ++g) {
        int h = g * 32 + lane;
        out[B_ * O_ + b * H_ + h]           = __fdiv_rn(s1c[g], (float)T_);
        out[B_ * O_ + B_ * H_ + b * H_ + h] = __fdiv_rn(s2c[g], (float)T_);
    }
}

// ---------------------------------------------------------------------------
// Kernel 3: A_norm = sum|w_h1h1*mask0| + sum|w_h2h2*mask1|  (fp32)
// ---------------------------------------------------------------------------
__global__ void anorm_kernel(const float* __restrict__ w11, const float* __restrict__ w22,
                             const float* __restrict__ mask, float* __restrict__ out)
{
    __shared__ float red[256];
    float s = 0.f;
    for (int i = threadIdx.x; i < H_ * H_; i += 256)
        s = __fadd_rn(s, __fadd_rn(fabsf(__fmul_rn(w11[i], mask[i])),
                                   fabsf(__fmul_rn(w22[i], mask[H_ * H_ + i]))));
    red[threadIdx.x] = s;
    __syncthreads();
    for (int o = 128; o > 0; o >>= 1) {
        if (threadIdx.x < o) red[threadIdx.x] = __fadd_rn(red[threadIdx.x], red[threadIdx.x + o]);
        __syncthreads();
    }
    if (threadIdx.x == 0) out[B_ * O_ + 2 * B_ * H_] = red[0];
}

// ---------------------------------------------------------------------------
extern "C" void kernel_launch(void* const* d_in, const int* in_sizes, int n_in,
                              void* d_out, int out_size)
{
    const float* x          = (const float*)d_in[0];
    const float* mask       = (const float*)d_in[1];
    const float* w_ih1      = (const float*)d_in[2];
    const float* b_ih1      = (const float*)d_in[3];
    const float* w_h1h1     = (const float*)d_in[4];
    const float* b_h1h1     = (const float*)d_in[5];
    const float* w_h1h2     = (const float*)d_in[6];
    const float* b_h1h2     = (const float*)d_in[7];
    const float* w_h2h2     = (const float*)d_in[8];
    const float* b_h2h2     = (const float*)d_in[9];
    const float* w_h2o      = (const float*)d_in[10];
    const float* b_h2o      = (const float*)d_in[11];
    const float* tau_adp_h1 = (const float*)d_in[12];
    const float* tau_adp_h2 = (const float*)d_in[13];
    const float* tau_m_h1   = (const float*)d_in[14];
    const float* tau_m_h2   = (const float*)d_in[15];
    const float* tau_m_o    = (const float*)d_in[16];
    const float* hid1_mem0  = (const float*)d_in[17];
    const float* hid2_mem0  = (const float*)d_in[18];
    const float* out_mem0   = (const float*)d_in[19];
    float* out = (float*)d_out;

    cudaFuncSetAttribute(scan_kernel, cudaFuncAttributeMaxDynamicSharedMemorySize,
                         SCAN_SMEM_BYTES);

    gemm_xin_kernel<<<(B_ * T_) / 128, 256>>>(x, w_ih1, b_ih1);
    scan_kernel<<<B_ / 4, 128, SCAN_SMEM_BYTES>>>(
        mask, w_h1h1, b_h1h1, w_h1h2, b_h1h2, w_h2h2, b_h2h2, w_h2o, b_h2o,
        tau_adp_h1, tau_adp_h2, tau_m_h1, tau_m_h2, tau_m_o,
        hid1_mem0, hid2_mem0, out_mem0, out);
    anorm_kernel<<<1, 256>>>(w_h1h1, w_h2h2, mask, out);
}